// round 2
// baseline (speedup 1.0000x reference)
#include <cuda_runtime.h>
#include <math.h>

#define Bb 2
#define Ss 2048
#define Dd 4096
#define Hh 32
#define HDh 128
#define HALFh 64
#define ALa 10
#define Mtok (Bb*Ss)

#define FBQ 64
#define FBKV 64
#define PSTR 68
#define FLASH_SMEM ((128*64 + 128*64 + 64*128 + 64*PSTR)*4)

// ---------------- scratch (static device globals; no allocation) ----------------
__device__ float g_q[Bb*Ss*Dd];
__device__ float g_k[Bb*Ss*Dd];
__device__ float g_v[Bb*Ss*Dd];
__device__ float g_attn[Bb*Ss*Dd];
__device__ float g_ak[Bb*ALa*Dd];
__device__ float g_av[Bb*ALa*Dd];

// ---------------- generic NT SGEMM: C[m,n] = sum_k A[m,k]*Bw[n,k] ----------------
// 128x128 tile, BK=8, 256 threads, 8x8 per thread
__global__ __launch_bounds__(256) void gemm_nt(
    const float* __restrict__ A, const float* __restrict__ Bw,
    float* __restrict__ C, int M, int N, int K)
{
    __shared__ __align__(16) float As[8][128];
    __shared__ __align__(16) float Bs[8][128];

    const int n0 = blockIdx.x * 128;
    const int m0 = blockIdx.y * 128;
    const int t  = threadIdx.x;
    const int tx = t & 15;
    const int ty = t >> 4;
    const int lr = t >> 1;          // 0..127 row within tile
    const int lc = (t & 1) << 2;    // 0 or 4

    float acc[8][8];
    #pragma unroll
    for (int i = 0; i < 8; i++)
        #pragma unroll
        for (int j = 0; j < 8; j++) acc[i][j] = 0.f;

    const bool arow_ok = (m0 + lr) < M;
    const float* Aptr = A + (size_t)(m0 + lr) * K + lc;
    const float* Bptr = Bw + (size_t)(n0 + lr) * K + lc;

    for (int k0 = 0; k0 < K; k0 += 8) {
        float4 avv = arow_ok ? *(const float4*)(Aptr + k0) : make_float4(0.f,0.f,0.f,0.f);
        float4 bvv = *(const float4*)(Bptr + k0);
        As[lc+0][lr] = avv.x; As[lc+1][lr] = avv.y; As[lc+2][lr] = avv.z; As[lc+3][lr] = avv.w;
        Bs[lc+0][lr] = bvv.x; Bs[lc+1][lr] = bvv.y; Bs[lc+2][lr] = bvv.z; Bs[lc+3][lr] = bvv.w;
        __syncthreads();

        #pragma unroll
        for (int kk = 0; kk < 8; kk++) {
            float a[8], b[8];
            *(float4*)&a[0] = *(const float4*)&As[kk][ty*8];
            *(float4*)&a[4] = *(const float4*)&As[kk][ty*8+4];
            *(float4*)&b[0] = *(const float4*)&Bs[kk][tx*8];
            *(float4*)&b[4] = *(const float4*)&Bs[kk][tx*8+4];
            #pragma unroll
            for (int i = 0; i < 8; i++)
                #pragma unroll
                for (int j = 0; j < 8; j++)
                    acc[i][j] += a[i] * b[j];
        }
        __syncthreads();
    }

    #pragma unroll
    for (int i = 0; i < 8; i++) {
        int row = m0 + ty*8 + i;
        if (row < M) {
            float4 r0 = make_float4(acc[i][0], acc[i][1], acc[i][2], acc[i][3]);
            float4 r1 = make_float4(acc[i][4], acc[i][5], acc[i][6], acc[i][7]);
            *(float4*)&C[(size_t)row * N + n0 + tx*8]     = r0;
            *(float4*)&C[(size_t)row * N + n0 + tx*8 + 4] = r1;
        }
    }
}

// ---------------- RoPE (in place on (B,S,H,HD) pairs) ----------------
__global__ void rope_kernel(float* __restrict__ T,
                            const float* __restrict__ cosT,
                            const float* __restrict__ sinT)
{
    int idx = blockIdx.x * blockDim.x + threadIdx.x;   // pair index (b,s,h,p)
    if (idx >= Bb*Ss*Hh*HALFh) return;
    int p = idx & (HALFh - 1);
    int s = (idx >> 11) & (Ss - 1);
    float c  = cosT[s*HALFh + p];
    float sn = sinT[s*HALFh + p];
    float2 v = *(float2*)&T[2*(size_t)idx];
    float2 r;
    r.x = v.x * c - v.y * sn;
    r.y = v.x * sn + v.y * c;
    *(float2*)&T[2*(size_t)idx] = r;
}

// ---------------- fused causal flash attention ----------------
// grid: (S/FBQ, B*H); block: 256 threads (16x16 micro grid, 4x4 scores, 4x8 output)
__global__ __launch_bounds__(256) void flash_kernel()
{
    extern __shared__ __align__(16) float sm[];
    float* Qs = sm;                  // [128][64] transposed (d-major)
    float* Ks = Qs + 128*64;         // [128][64] transposed
    float* Vs = Ks + 128*64;         // [64][128] natural
    float* Ps = Vs + 64*128;         // [64][PSTR] row-major (i, j)

    const int t  = threadIdx.x;
    const int tx = t & 15;
    const int ty = t >> 4;
    const int ty4 = ty * 4;
    const int tx4 = tx * 4;
    const int tx8 = tx * 8;
    const int bh = blockIdx.y;
    const int b = bh >> 5, h = bh & 31;
    const int q0 = blockIdx.x * FBQ;
    const float rscale = 0.08838834764831844f;  // 1/sqrt(128)

    const size_t headbase = (size_t)b * Ss * Dd + (size_t)h * HDh;
    const float* Qg = g_q + headbase + (size_t)q0 * Dd;

    // load Q transposed: Qs[d][i]
    #pragma unroll
    for (int r = 0; r < 8; r++) {
        int idx = t + r*256;
        int i  = idx & 63;
        int dg = (idx >> 6) << 2;
        float4 v = *(const float4*)&Qg[(size_t)i * Dd + dg];
        Qs[(dg+0)*64 + i] = v.x;
        Qs[(dg+1)*64 + i] = v.y;
        Qs[(dg+2)*64 + i] = v.z;
        Qs[(dg+3)*64 + i] = v.w;
    }

    float m_run[4], l_run[4], o[4][8];
    #pragma unroll
    for (int ii = 0; ii < 4; ii++) {
        m_run[ii] = -1e30f; l_run[ii] = 0.f;
        #pragma unroll
        for (int dd = 0; dd < 8; dd++) o[ii][dd] = 0.f;
    }

    for (int j0 = 0; j0 <= q0; j0 += FBKV) {
        __syncthreads();   // prior iteration's P·V reads complete before overwrite
        const float* Kg = g_k + headbase + (size_t)j0 * Dd;
        const float* Vg = g_v + headbase + (size_t)j0 * Dd;
        #pragma unroll
        for (int r = 0; r < 8; r++) {
            int idx = t + r*256;
            int i  = idx & 63;
            int dg = (idx >> 6) << 2;
            float4 kv = *(const float4*)&Kg[(size_t)i * Dd + dg];
            Ks[(dg+0)*64 + i] = kv.x;
            Ks[(dg+1)*64 + i] = kv.y;
            Ks[(dg+2)*64 + i] = kv.z;
            Ks[(dg+3)*64 + i] = kv.w;
            int j2  = idx >> 5;
            int dg2 = (idx & 31) << 2;
            float4 vv = *(const float4*)&Vg[(size_t)j2 * Dd + dg2];
            *(float4*)&Vs[j2*128 + dg2] = vv;
        }
        __syncthreads();

        // scores: s[ii][jj] = q_i . k_j
        float s[4][4];
        #pragma unroll
        for (int ii = 0; ii < 4; ii++)
            #pragma unroll
            for (int jj = 0; jj < 4; jj++) s[ii][jj] = 0.f;

        #pragma unroll 4
        for (int d = 0; d < 128; d++) {
            float4 qa = *(const float4*)&Qs[d*64 + ty4];
            float4 kb = *(const float4*)&Ks[d*64 + tx4];
            s[0][0] += qa.x*kb.x; s[0][1] += qa.x*kb.y; s[0][2] += qa.x*kb.z; s[0][3] += qa.x*kb.w;
            s[1][0] += qa.y*kb.x; s[1][1] += qa.y*kb.y; s[1][2] += qa.y*kb.z; s[1][3] += qa.y*kb.w;
            s[2][0] += qa.z*kb.x; s[2][1] += qa.z*kb.y; s[2][2] += qa.z*kb.z; s[2][3] += qa.z*kb.w;
            s[3][0] += qa.w*kb.x; s[3][1] += qa.w*kb.y; s[3][2] += qa.w*kb.z; s[3][3] += qa.w*kb.w;
        }

        // scale + causal mask (only bites on the diagonal block)
        #pragma unroll
        for (int ii = 0; ii < 4; ii++) {
            int ig = q0 + ty4 + ii;
            #pragma unroll
            for (int jj = 0; jj < 4; jj++) {
                int jg = j0 + tx4 + jj;
                s[ii][jj] = (jg > ig) ? -1e30f : s[ii][jj] * rscale;
            }
        }

        // online softmax (row split across 16 tx lanes within warp half)
        float corr[4];
        #pragma unroll
        for (int ii = 0; ii < 4; ii++) {
            float mx = fmaxf(fmaxf(s[ii][0], s[ii][1]), fmaxf(s[ii][2], s[ii][3]));
            #pragma unroll
            for (int off = 8; off >= 1; off >>= 1)
                mx = fmaxf(mx, __shfl_xor_sync(0xffffffffu, mx, off));
            float mn = fmaxf(m_run[ii], mx);
            float co = __expf(m_run[ii] - mn);
            float sum = 0.f;
            #pragma unroll
            for (int jj = 0; jj < 4; jj++) {
                float e = __expf(s[ii][jj] - mn);
                s[ii][jj] = e;
                sum += e;
            }
            #pragma unroll
            for (int off = 8; off >= 1; off >>= 1)
                sum += __shfl_xor_sync(0xffffffffu, sum, off);
            l_run[ii] = l_run[ii] * co + sum;
            m_run[ii] = mn;
            corr[ii] = co;
        }
        #pragma unroll
        for (int ii = 0; ii < 4; ii++)
            #pragma unroll
            for (int dd = 0; dd < 8; dd++) o[ii][dd] *= corr[ii];

        // write P (row-major [i][j], vectorized along j)
        #pragma unroll
        for (int ii = 0; ii < 4; ii++) {
            float4 pv = make_float4(s[ii][0], s[ii][1], s[ii][2], s[ii][3]);
            *(float4*)&Ps[(ty4 + ii)*PSTR + tx4] = pv;
        }
        __syncthreads();

        // O += P . V
        #pragma unroll 2
        for (int j = 0; j < FBKV; j++) {
            float4 v0 = *(const float4*)&Vs[j*128 + tx8];
            float4 v1 = *(const float4*)&Vs[j*128 + tx8 + 4];
            #pragma unroll
            for (int ii = 0; ii < 4; ii++) {
                float pv = Ps[(ty4 + ii)*PSTR + j];
                o[ii][0] += pv * v0.x; o[ii][1] += pv * v0.y;
                o[ii][2] += pv * v0.z; o[ii][3] += pv * v0.w;
                o[ii][4] += pv * v1.x; o[ii][5] += pv * v1.y;
                o[ii][6] += pv * v1.z; o[ii][7] += pv * v1.w;
            }
        }
    }

    // epilogue: normalize + store to (B,S,D) layout
    float* Og = g_attn + headbase + (size_t)q0 * Dd;
    #pragma unroll
    for (int ii = 0; ii < 4; ii++) {
        float inv = 1.f / l_run[ii];
        int i = ty4 + ii;
        float4 r0 = make_float4(o[ii][0]*inv, o[ii][1]*inv, o[ii][2]*inv, o[ii][3]*inv);
        float4 r1 = make_float4(o[ii][4]*inv, o[ii][5]*inv, o[ii][6]*inv, o[ii][7]*inv);
        *(float4*)&Og[(size_t)i * Dd + tx8]     = r0;
        *(float4*)&Og[(size_t)i * Dd + tx8 + 4] = r1;
    }
}

// ---------------- adapter attention: out += tanh(gate_h) * softmax(q.a_k^T/sqrt(HD)) @ a_v ----------------
// grid: (S/4, B*H); block 128 (4 warps, one query row per warp)
__global__ __launch_bounds__(128) void adapter_kernel(const float* __restrict__ gate)
{
    __shared__ __align__(16) float ak[ALa][HDh];
    __shared__ __align__(16) float av[ALa][HDh];
    const int t = threadIdx.x;
    const int bh = blockIdx.y;
    const int b = bh >> 5, h = bh & 31;
    const int s0 = blockIdx.x * 4;

    #pragma unroll
    for (int r = 0; r < ALa; r++) {
        int idx = t + r*128;
        int j = idx >> 7, d = idx & 127;
        ak[j][d] = g_ak[(size_t)(b*ALa + j) * Dd + h*HDh + d];
        av[j][d] = g_av[(size_t)(b*ALa + j) * Dd + h*HDh + d];
    }
    __syncthreads();

    const int w = t >> 5, lane = t & 31;
    const int s = s0 + w;
    const size_t base = (size_t)(b*Ss + s) * Dd + h*HDh;
    const float rscale = 0.08838834764831844f;

    float4 qv = *(const float4*)&g_q[base + lane*4];
    float sc[ALa];
    #pragma unroll
    for (int j = 0; j < ALa; j++) {
        float d0 = qv.x*ak[j][lane*4+0] + qv.y*ak[j][lane*4+1]
                 + qv.z*ak[j][lane*4+2] + qv.w*ak[j][lane*4+3];
        #pragma unroll
        for (int off = 16; off >= 1; off >>= 1)
            d0 += __shfl_xor_sync(0xffffffffu, d0, off);
        sc[j] = d0 * rscale;
    }
    float mx = sc[0];
    #pragma unroll
    for (int j = 1; j < ALa; j++) mx = fmaxf(mx, sc[j]);
    float sum = 0.f;
    #pragma unroll
    for (int j = 0; j < ALa; j++) { sc[j] = __expf(sc[j] - mx); sum += sc[j]; }
    float inv = 1.f / sum;
    float g = tanhf(gate[h]);

    float acc[4] = {0.f, 0.f, 0.f, 0.f};
    #pragma unroll
    for (int j = 0; j < ALa; j++) {
        float p = sc[j] * inv;
        acc[0] += p * av[j][lane*4+0];
        acc[1] += p * av[j][lane*4+1];
        acc[2] += p * av[j][lane*4+2];
        acc[3] += p * av[j][lane*4+3];
    }
    float4 ov = *(float4*)&g_attn[base + lane*4];
    ov.x += g*acc[0]; ov.y += g*acc[1]; ov.z += g*acc[2]; ov.w += g*acc[3];
    *(float4*)&g_attn[base + lane*4] = ov;
}

// ---------------- host ----------------
extern "C" void kernel_launch(void* const* d_in, const int* in_sizes, int n_in,
                              void* d_out, int out_size)
{
    (void)in_sizes; (void)n_in; (void)out_size;
    const float* x       = (const float*)d_in[0];
    const float* cosT    = (const float*)d_in[2];
    const float* sinT    = (const float*)d_in[3];
    const float* wq      = (const float*)d_in[4];
    const float* wk      = (const float*)d_in[5];
    const float* wv      = (const float*)d_in[6];
    const float* wo      = (const float*)d_in[7];
    const float* gate    = (const float*)d_in[8];
    const float* adapter = (const float*)d_in[9];
    float* out = (float*)d_out;

    float *qp, *kp, *vp, *attnp, *akp, *avp;
    cudaGetSymbolAddress((void**)&qp,    g_q);
    cudaGetSymbolAddress((void**)&kp,    g_k);
    cudaGetSymbolAddress((void**)&vp,    g_v);
    cudaGetSymbolAddress((void**)&attnp, g_attn);
    cudaGetSymbolAddress((void**)&akp,   g_ak);
    cudaGetSymbolAddress((void**)&avp,   g_av);

    cudaFuncSetAttribute(flash_kernel, cudaFuncAttributeMaxDynamicSharedMemorySize, FLASH_SMEM);

    dim3 blk(256);
    dim3 gbig(Dd/128, Mtok/128);

    gemm_nt<<<gbig, blk>>>(x, wq, qp, Mtok, Dd, Dd);
    gemm_nt<<<gbig, blk>>>(x, wk, kp, Mtok, Dd, Dd);
    gemm_nt<<<gbig, blk>>>(x, wv, vp, Mtok, Dd, Dd);
    gemm_nt<<<dim3(Dd/128, 1), blk>>>(adapter, wk, akp, Bb*ALa, Dd, Dd);
    gemm_nt<<<dim3(Dd/128, 1), blk>>>(adapter, wv, avp, Bb*ALa, Dd, Dd);

    int npairs = Bb*Ss*Hh*HALFh;
    rope_kernel<<<npairs/256, 256>>>(qp, cosT, sinT);
    rope_kernel<<<npairs/256, 256>>>(kp, cosT, sinT);

    flash_kernel<<<dim3(Ss/FBQ, Bb*Hh), 256, FLASH_SMEM>>>();
    adapter_kernel<<<dim3(Ss/4, Bb*Hh), 128>>>(gate);

    gemm_nt<<<gbig, blk>>>(attnp, wo, out, Mtok, Dd, Dd);
}

// round 4
// speedup vs baseline: 2.5949x; 2.5949x over previous
#include <cuda_runtime.h>
#include <math.h>
#include <stdint.h>

#define Bb 2
#define Ss 2048
#define Dd 4096
#define Hh 32
#define HDh 128
#define HALFh 64
#define ALa 10
#define Mtok (Bb*Ss)

#define FBQ 64
#define FBKV 64
#define PSTR 68
#define FLASH_SMEM ((128*64 + 128*64 + 64*128 + 64*PSTR)*4)

// ---- tf32 mma.sync GEMM config ----
#define BM 128
#define BN 128
#define BK 32
#define KSTRD 36                      // floats per smem row (32 + 4 pad) -> 144B
#define STAGE_FLOATS (BM*KSTRD)       // 4608 floats (18432 B) per operand
#define STAGE_BYTES (2*STAGE_FLOATS*4)
#define NSTAGE 4
#define GEMM_SMEM (NSTAGE*STAGE_BYTES)  // 147456 B

// ---------------- scratch (static device globals; no allocation) ----------------
__device__ float g_q[Bb*Ss*Dd];
__device__ float g_k[Bb*Ss*Dd];
__device__ float g_v[Bb*Ss*Dd];
__device__ float g_attn[Bb*Ss*Dd];
__device__ float g_ak[Bb*ALa*Dd];
__device__ float g_av[Bb*ALa*Dd];

__device__ __forceinline__ uint32_t s2u(const void* p){
    uint32_t r;
    asm("{ .reg .u64 t; cvta.to.shared.u64 t, %1; cvt.u32.u64 %0, t; }" : "=r"(r) : "l"(p));
    return r;
}

__device__ __forceinline__ void ldsm_x4(uint32_t* r, uint32_t addr){
    asm volatile("ldmatrix.sync.aligned.m8n8.x4.shared.b16 {%0,%1,%2,%3}, [%4];"
                 : "=r"(r[0]), "=r"(r[1]), "=r"(r[2]), "=r"(r[3]) : "r"(addr));
}

__device__ __forceinline__ uint32_t f2tf(uint32_t x){
    uint32_t y;
    asm("cvt.rna.tf32.f32 %0, %1;" : "=r"(y) : "r"(x));
    return y;
}

__device__ __forceinline__ void mma_tf32(float* d, const uint32_t* a, const uint32_t* b){
    asm volatile(
        "mma.sync.aligned.m16n8k8.row.col.f32.tf32.tf32.f32 "
        "{%0,%1,%2,%3}, {%4,%5,%6,%7}, {%8,%9}, {%0,%1,%2,%3};"
        : "+f"(d[0]), "+f"(d[1]), "+f"(d[2]), "+f"(d[3])
        : "r"(a[0]), "r"(a[1]), "r"(a[2]), "r"(a[3]), "r"(b[0]), "r"(b[1]));
}

// ---------------- tf32 mma.sync NT GEMM: C[m,n] = sum_k A[m,k]*Bw[n,k] ----------------
__global__ __launch_bounds__(256) void gemm_mma(
    const float* __restrict__ A, const float* __restrict__ Bw,
    float* __restrict__ C, int M, int N, int K)
{
    extern __shared__ float sm_g[];
    const uint32_t sbase = s2u(sm_g);
    const int t = threadIdx.x;
    const int m0 = blockIdx.y * BM;
    const int n0 = blockIdx.x * BN;
    const int NCH = K / BK;

    const int lane = t & 31;
    const int wid  = t >> 5;
    const int wm   = wid & 3;      // 4 warps along M (32 rows each)
    const int wn   = wid >> 2;     // 2 warps along N (64 cols each)

    // cp.async geometry: idx = t + i*256 -> row = idx>>3, quad = t&7
    const int ldr = t >> 3;
    const int ldq = t & 7;

    float d[2][8][4];
    #pragma unroll
    for (int mt = 0; mt < 2; mt++)
        #pragma unroll
        for (int nt = 0; nt < 8; nt++)
            #pragma unroll
            for (int c = 0; c < 4; c++) d[mt][nt][c] = 0.f;

    // fragment smem byte offsets (within stage operand base)
    const uint32_t aOff = (uint32_t)(wm*32 + (lane & 15)) * 144u + ((lane >> 4) << 4);
    const uint32_t bOff = (uint32_t)(wn*64 + ((lane >> 4) << 3) + (lane & 7)) * 144u
                          + (((lane >> 3) & 1) << 4);

    // ---------------- prefetch lambda ----------------
    auto prefetch = [&](int chunk, int stage){
        const int k0 = chunk * BK;
        const uint32_t sA = sbase + (uint32_t)stage * STAGE_BYTES;
        const uint32_t sB = sA + STAGE_FLOATS*4;
        #pragma unroll
        for (int i = 0; i < 4; i++) {
            int row = ldr + i*32;
            int ar = m0 + row; if (ar > M-1) ar = M-1;
            const float* ga = A  + (size_t)ar * K + k0 + ldq*4;
            const float* gb = Bw + (size_t)(n0 + row) * K + k0 + ldq*4;
            uint32_t so = (uint32_t)row * 144u + (uint32_t)ldq * 16u;
            asm volatile("cp.async.cg.shared.global [%0], [%1], 16;" :: "r"(sA + so), "l"(ga));
            asm volatile("cp.async.cg.shared.global [%0], [%1], 16;" :: "r"(sB + so), "l"(gb));
        }
        asm volatile("cp.async.commit_group;" ::: "memory");
    };

    #pragma unroll
    for (int p = 0; p < NSTAGE; p++) prefetch(p, p);

    for (int n = 0; n < NCH; n++) {
        const int s = n & (NSTAGE - 1);
        asm volatile("cp.async.wait_group %0;" :: "n"(NSTAGE-1) : "memory");
        __syncthreads();

        const uint32_t sA = sbase + (uint32_t)s * STAGE_BYTES;
        const uint32_t sB = sA + STAGE_FLOATS*4;

        #pragma unroll
        for (int ks = 0; ks < 4; ks++) {
            const uint32_t kb = (uint32_t)ks * 32u;   // 8 floats
            uint32_t af[2][4], bf[8][2];
            #pragma unroll
            for (int mt = 0; mt < 2; mt++) {
                ldsm_x4(af[mt], sA + aOff + (uint32_t)mt*(16u*144u) + kb);
                #pragma unroll
                for (int c = 0; c < 4; c++) af[mt][c] = f2tf(af[mt][c]);
            }
            #pragma unroll
            for (int ntp = 0; ntp < 4; ntp++) {
                uint32_t r[4];
                ldsm_x4(r, sB + bOff + (uint32_t)ntp*(16u*144u) + kb);
                bf[2*ntp][0]   = f2tf(r[0]);
                bf[2*ntp][1]   = f2tf(r[1]);
                bf[2*ntp+1][0] = f2tf(r[2]);
                bf[2*ntp+1][1] = f2tf(r[3]);
            }
            #pragma unroll
            for (int mt = 0; mt < 2; mt++)
                #pragma unroll
                for (int nt = 0; nt < 8; nt++)
                    mma_tf32(d[mt][nt], af[mt], bf[nt]);
        }
        __syncthreads();

        int pn = n + NSTAGE; if (pn >= NCH) pn = 0;
        prefetch(pn, s);
    }

    // ---------------- epilogue ----------------
    const int g  = lane >> 2;
    const int tq = lane & 3;
    #pragma unroll
    for (int mt = 0; mt < 2; mt++) {
        int row = m0 + wm*32 + mt*16 + g;
        #pragma unroll
        for (int nt = 0; nt < 8; nt++) {
            int col = n0 + wn*64 + nt*8 + 2*tq;
            if (row < M)
                *(float2*)&C[(size_t)row * N + col] = make_float2(d[mt][nt][0], d[mt][nt][1]);
            if (row + 8 < M)
                *(float2*)&C[(size_t)(row+8) * N + col] = make_float2(d[mt][nt][2], d[mt][nt][3]);
        }
    }
}

// ---------------- RoPE ----------------
__global__ void rope_kernel(float* __restrict__ T,
                            const float* __restrict__ cosT,
                            const float* __restrict__ sinT)
{
    int idx = blockIdx.x * blockDim.x + threadIdx.x;
    if (idx >= Bb*Ss*Hh*HALFh) return;
    int p = idx & (HALFh - 1);
    int s = (idx >> 11) & (Ss - 1);
    float c  = cosT[s*HALFh + p];
    float sn = sinT[s*HALFh + p];
    float2 v = *(float2*)&T[2*(size_t)idx];
    float2 r;
    r.x = v.x * c - v.y * sn;
    r.y = v.x * sn + v.y * c;
    *(float2*)&T[2*(size_t)idx] = r;
}

// ---------------- fused causal flash attention (SIMT, proven) ----------------
__global__ __launch_bounds__(256) void flash_kernel()
{
    extern __shared__ __align__(16) float sm[];
    float* Qs = sm;
    float* Ks = Qs + 128*64;
    float* Vs = Ks + 128*64;
    float* Ps = Vs + 64*128;

    const int t  = threadIdx.x;
    const int tx = t & 15;
    const int ty = t >> 4;
    const int ty4 = ty * 4;
    const int tx4 = tx * 4;
    const int tx8 = tx * 8;
    const int bh = blockIdx.y;
    const int b = bh >> 5, h = bh & 31;
    const int q0 = blockIdx.x * FBQ;
    const float rscale = 0.08838834764831844f;

    const size_t headbase = (size_t)b * Ss * Dd + (size_t)h * HDh;
    const float* Qg = g_q + headbase + (size_t)q0 * Dd;

    #pragma unroll
    for (int r = 0; r < 8; r++) {
        int idx = t + r*256;
        int i  = idx & 63;
        int dg = (idx >> 6) << 2;
        float4 v = *(const float4*)&Qg[(size_t)i * Dd + dg];
        Qs[(dg+0)*64 + i] = v.x;
        Qs[(dg+1)*64 + i] = v.y;
        Qs[(dg+2)*64 + i] = v.z;
        Qs[(dg+3)*64 + i] = v.w;
    }

    float m_run[4], l_run[4], o[4][8];
    #pragma unroll
    for (int ii = 0; ii < 4; ii++) {
        m_run[ii] = -1e30f; l_run[ii] = 0.f;
        #pragma unroll
        for (int dd = 0; dd < 8; dd++) o[ii][dd] = 0.f;
    }

    for (int j0 = 0; j0 <= q0; j0 += FBKV) {
        __syncthreads();
        const float* Kg = g_k + headbase + (size_t)j0 * Dd;
        const float* Vg = g_v + headbase + (size_t)j0 * Dd;
        #pragma unroll
        for (int r = 0; r < 8; r++) {
            int idx = t + r*256;
            int i  = idx & 63;
            int dg = (idx >> 6) << 2;
            float4 kv = *(const float4*)&Kg[(size_t)i * Dd + dg];
            Ks[(dg+0)*64 + i] = kv.x;
            Ks[(dg+1)*64 + i] = kv.y;
            Ks[(dg+2)*64 + i] = kv.z;
            Ks[(dg+3)*64 + i] = kv.w;
            int j2  = idx >> 5;
            int dg2 = (idx & 31) << 2;
            float4 vv = *(const float4*)&Vg[(size_t)j2 * Dd + dg2];
            *(float4*)&Vs[j2*128 + dg2] = vv;
        }
        __syncthreads();

        float s[4][4];
        #pragma unroll
        for (int ii = 0; ii < 4; ii++)
            #pragma unroll
            for (int jj = 0; jj < 4; jj++) s[ii][jj] = 0.f;

        #pragma unroll 4
        for (int d = 0; d < 128; d++) {
            float4 qa = *(const float4*)&Qs[d*64 + ty4];
            float4 kb = *(const float4*)&Ks[d*64 + tx4];
            s[0][0] += qa.x*kb.x; s[0][1] += qa.x*kb.y; s[0][2] += qa.x*kb.z; s[0][3] += qa.x*kb.w;
            s[1][0] += qa.y*kb.x; s[1][1] += qa.y*kb.y; s[1][2] += qa.y*kb.z; s[1][3] += qa.y*kb.w;
            s[2][0] += qa.z*kb.x; s[2][1] += qa.z*kb.y; s[2][2] += qa.z*kb.z; s[2][3] += qa.z*kb.w;
            s[3][0] += qa.w*kb.x; s[3][1] += qa.w*kb.y; s[3][2] += qa.w*kb.z; s[3][3] += qa.w*kb.w;
        }

        #pragma unroll
        for (int ii = 0; ii < 4; ii++) {
            int ig = q0 + ty4 + ii;
            #pragma unroll
            for (int jj = 0; jj < 4; jj++) {
                int jg = j0 + tx4 + jj;
                s[ii][jj] = (jg > ig) ? -1e30f : s[ii][jj] * rscale;
            }
        }

        float corr[4];
        #pragma unroll
        for (int ii = 0; ii < 4; ii++) {
            float mx = fmaxf(fmaxf(s[ii][0], s[ii][1]), fmaxf(s[ii][2], s[ii][3]));
            #pragma unroll
            for (int off = 8; off >= 1; off >>= 1)
                mx = fmaxf(mx, __shfl_xor_sync(0xffffffffu, mx, off));
            float mn = fmaxf(m_run[ii], mx);
            float co = __expf(m_run[ii] - mn);
            float sum = 0.f;
            #pragma unroll
            for (int jj = 0; jj < 4; jj++) {
                float e = __expf(s[ii][jj] - mn);
                s[ii][jj] = e;
                sum += e;
            }
            #pragma unroll
            for (int off = 8; off >= 1; off >>= 1)
                sum += __shfl_xor_sync(0xffffffffu, sum, off);
            l_run[ii] = l_run[ii] * co + sum;
            m_run[ii] = mn;
            corr[ii] = co;
        }
        #pragma unroll
        for (int ii = 0; ii < 4; ii++)
            #pragma unroll
            for (int dd = 0; dd < 8; dd++) o[ii][dd] *= corr[ii];

        #pragma unroll
        for (int ii = 0; ii < 4; ii++) {
            float4 pv = make_float4(s[ii][0], s[ii][1], s[ii][2], s[ii][3]);
            *(float4*)&Ps[(ty4 + ii)*PSTR + tx4] = pv;
        }
        __syncthreads();

        #pragma unroll 2
        for (int j = 0; j < FBKV; j++) {
            float4 v0 = *(const float4*)&Vs[j*128 + tx8];
            float4 v1 = *(const float4*)&Vs[j*128 + tx8 + 4];
            #pragma unroll
            for (int ii = 0; ii < 4; ii++) {
                float pv = Ps[(ty4 + ii)*PSTR + j];
                o[ii][0] += pv * v0.x; o[ii][1] += pv * v0.y;
                o[ii][2] += pv * v0.z; o[ii][3] += pv * v0.w;
                o[ii][4] += pv * v1.x; o[ii][5] += pv * v1.y;
                o[ii][6] += pv * v1.z; o[ii][7] += pv * v1.w;
            }
        }
    }

    float* Og = g_attn + headbase + (size_t)q0 * Dd;
    #pragma unroll
    for (int ii = 0; ii < 4; ii++) {
        float inv = 1.f / l_run[ii];
        int i = ty4 + ii;
        float4 r0 = make_float4(o[ii][0]*inv, o[ii][1]*inv, o[ii][2]*inv, o[ii][3]*inv);
        float4 r1 = make_float4(o[ii][4]*inv, o[ii][5]*inv, o[ii][6]*inv, o[ii][7]*inv);
        *(float4*)&Og[(size_t)i * Dd + tx8]     = r0;
        *(float4*)&Og[(size_t)i * Dd + tx8 + 4] = r1;
    }
}

// ---------------- adapter attention ----------------
__global__ __launch_bounds__(128) void adapter_kernel(const float* __restrict__ gate)
{
    __shared__ __align__(16) float ak[ALa][HDh];
    __shared__ __align__(16) float av[ALa][HDh];
    const int t = threadIdx.x;
    const int bh = blockIdx.y;
    const int b = bh >> 5, h = bh & 31;
    const int s0 = blockIdx.x * 4;

    #pragma unroll
    for (int r = 0; r < ALa; r++) {
        int idx = t + r*128;
        int j = idx >> 7, d = idx & 127;
        ak[j][d] = g_ak[(size_t)(b*ALa + j) * Dd + h*HDh + d];
        av[j][d] = g_av[(size_t)(b*ALa + j) * Dd + h*HDh + d];
    }
    __syncthreads();

    const int w = t >> 5, lane = t & 31;
    const int s = s0 + w;
    const size_t base = (size_t)(b*Ss + s) * Dd + h*HDh;
    const float rscale = 0.08838834764831844f;

    float4 qv = *(const float4*)&g_q[base + lane*4];
    float sc[ALa];
    #pragma unroll
    for (int j = 0; j < ALa; j++) {
        float d0 = qv.x*ak[j][lane*4+0] + qv.y*ak[j][lane*4+1]
                 + qv.z*ak[j][lane*4+2] + qv.w*ak[j][lane*4+3];
        #pragma unroll
        for (int off = 16; off >= 1; off >>= 1)
            d0 += __shfl_xor_sync(0xffffffffu, d0, off);
        sc[j] = d0 * rscale;
    }
    float mx = sc[0];
    #pragma unroll
    for (int j = 1; j < ALa; j++) mx = fmaxf(mx, sc[j]);
    float sum = 0.f;
    #pragma unroll
    for (int j = 0; j < ALa; j++) { sc[j] = __expf(sc[j] - mx); sum += sc[j]; }
    float inv = 1.f / sum;
    float g = tanhf(gate[h]);

    float acc[4] = {0.f, 0.f, 0.f, 0.f};
    #pragma unroll
    for (int j = 0; j < ALa; j++) {
        float p = sc[j] * inv;
        acc[0] += p * av[j][lane*4+0];
        acc[1] += p * av[j][lane*4+1];
        acc[2] += p * av[j][lane*4+2];
        acc[3] += p * av[j][lane*4+3];
    }
    float4 ov = *(float4*)&g_attn[base + lane*4];
    ov.x += g*acc[0]; ov.y += g*acc[1]; ov.z += g*acc[2]; ov.w += g*acc[3];
    *(float4*)&g_attn[base + lane*4] = ov;
}

// ---------------- host ----------------
extern "C" void kernel_launch(void* const* d_in, const int* in_sizes, int n_in,
                              void* d_out, int out_size)
{
    (void)in_sizes; (void)n_in; (void)out_size;
    const float* x       = (const float*)d_in[0];
    const float* cosT    = (const float*)d_in[2];
    const float* sinT    = (const float*)d_in[3];
    const float* wq      = (const float*)d_in[4];
    const float* wk      = (const float*)d_in[5];
    const float* wv      = (const float*)d_in[6];
    const float* wo      = (const float*)d_in[7];
    const float* gate    = (const float*)d_in[8];
    const float* adapter = (const float*)d_in[9];
    float* out = (float*)d_out;

    float *qp, *kp, *vp, *attnp, *akp, *avp;
    cudaGetSymbolAddress((void**)&qp,    g_q);
    cudaGetSymbolAddress((void**)&kp,    g_k);
    cudaGetSymbolAddress((void**)&vp,    g_v);
    cudaGetSymbolAddress((void**)&attnp, g_attn);
    cudaGetSymbolAddress((void**)&akp,   g_ak);
    cudaGetSymbolAddress((void**)&avp,   g_av);

    cudaFuncSetAttribute(gemm_mma, cudaFuncAttributeMaxDynamicSharedMemorySize, GEMM_SMEM);
    cudaFuncSetAttribute(flash_kernel, cudaFuncAttributeMaxDynamicSharedMemorySize, FLASH_SMEM);

    dim3 gbig(Dd/BN, Mtok/BM);

    gemm_mma<<<gbig, 256, GEMM_SMEM>>>(x, wq, qp, Mtok, Dd, Dd);
    gemm_mma<<<gbig, 256, GEMM_SMEM>>>(x, wk, kp, Mtok, Dd, Dd);
    gemm_mma<<<gbig, 256, GEMM_SMEM>>>(x, wv, vp, Mtok, Dd, Dd);
    gemm_mma<<<dim3(Dd/BN, 1), 256, GEMM_SMEM>>>(adapter, wk, akp, Bb*ALa, Dd, Dd);
    gemm_mma<<<dim3(Dd/BN, 1), 256, GEMM_SMEM>>>(adapter, wv, avp, Bb*ALa, Dd, Dd);

    int npairs = Bb*Ss*Hh*HALFh;
    rope_kernel<<<npairs/256, 256>>>(qp, cosT, sinT);
    rope_kernel<<<npairs/256, 256>>>(kp, cosT, sinT);

    flash_kernel<<<dim3(Ss/FBQ, Bb*Hh), 256, FLASH_SMEM>>>();
    adapter_kernel<<<dim3(Ss/4, Bb*Hh), 128>>>(gate);

    gemm_mma<<<gbig, 256, GEMM_SMEM>>>(attnp, wo, out, Mtok, Dd, Dd);
}